// round 1
// baseline (speedup 1.0000x reference)
#include <cuda_runtime.h>
#include <math.h>

// Problem constants
#define B_SZ   8192
#define IN_SZ  1024
#define OUT_SZ 1024
#define D_SZ   4
#define NSTEPS 8
#define NCOL   (B_SZ * D_SZ)      /* 32768 columns of the step GEMM */
#define EPS_N  1e-12f

// GEMM tiling
#define BM 128
#define BN 128
#define BK 8
#define NTHREADS 256

// Ping-pong state buffers: V[s][i][b*4+d]  (OUT-major, D innermost)
__device__ float g_V[2][(long)OUT_SZ * NCOL];   // 2 x 128 MB
__device__ float g_Kt[OUT_SZ * OUT_SZ];         // tanh(coupling)

// ---------------------------------------------------------------------------
// K = tanh(coupling)
// ---------------------------------------------------------------------------
__global__ void tanh_kernel(const float* __restrict__ coup) {
    int i = blockIdx.x * 256 + threadIdx.x;
    g_Kt[i] = tanhf(coup[i]);
}

// ---------------------------------------------------------------------------
// Initial projection: C2[m,b] = sum_k W[k*4096+m] * x[b*1024+k],  m=(i,d)
// Output normalized over d and stored as V[0][i][b*4+d].
// ---------------------------------------------------------------------------
__global__ __launch_bounds__(NTHREADS, 2)
void init_kernel(const float* __restrict__ x, const float* __restrict__ W) {
    __shared__ float As[BK][BM];        // As[kk][mm] = W[(k0+kk)*4096 + m0+mm]
    __shared__ float Bs[BK][BN + 4];    // Bs[kk][bb] = x[(n0+bb)*1024 + k0+kk]

    const int m0 = blockIdx.y * BM;     // (i,d) row block
    const int n0 = blockIdx.x * BN;     // b column block
    const int tid = threadIdx.x;
    const int tc = tid & 15;
    const int tr = tid >> 4;

    // A tile load (direct, coalesced): 256 threads x float4
    const int a_kk = tid >> 5;                  // 0..7
    const int a_mm = (tid & 31) * 4;
    // B tile load (transposed): 2 threads per b row, 4 k each
    const int b_bb = tid >> 1;                  // 0..127
    const int b_kq = (tid & 1) * 4;

    const float* Aptr = W + (long)a_kk * (OUT_SZ * D_SZ) + m0 + a_mm;
    const float* Bptr = x + (long)(n0 + b_bb) * IN_SZ + b_kq;

    float acc[8][8];
#pragma unroll
    for (int r = 0; r < 8; r++)
#pragma unroll
        for (int c = 0; c < 8; c++) acc[r][c] = 0.f;

    float4 pa = *(const float4*)(Aptr);
    float4 pb = *(const float4*)(Bptr);

    for (int k0 = 0; k0 < IN_SZ; k0 += BK) {
        *(float4*)&As[a_kk][a_mm] = pa;
        Bs[b_kq + 0][b_bb] = pb.x;
        Bs[b_kq + 1][b_bb] = pb.y;
        Bs[b_kq + 2][b_bb] = pb.z;
        Bs[b_kq + 3][b_bb] = pb.w;
        __syncthreads();
        if (k0 + BK < IN_SZ) {
            pa = *(const float4*)(Aptr + (long)(k0 + BK) * (OUT_SZ * D_SZ));
            pb = *(const float4*)(Bptr + (k0 + BK));
        }
#pragma unroll
        for (int kk = 0; kk < BK; kk++) {
            float a[8], b[8];
            *(float4*)&a[0] = *(const float4*)&As[kk][tr * 4];
            *(float4*)&a[4] = *(const float4*)&As[kk][64 + tr * 4];
            *(float4*)&b[0] = *(const float4*)&Bs[kk][tc * 4];
            *(float4*)&b[4] = *(const float4*)&Bs[kk][64 + tc * 4];
#pragma unroll
            for (int r = 0; r < 8; r++)
#pragma unroll
                for (int c = 0; c < 8; c++)
                    acc[r][c] = fmaf(a[r], b[c], acc[r][c]);
        }
        __syncthreads();
    }

    // Epilogue: rows are (i,d); normalize groups of 4 rows (fixed i, d=0..3).
#pragma unroll
    for (int rh = 0; rh < 2; rh++) {
        const int m = m0 + rh * 64 + tr * 4;    // 4-aligned -> i = m>>2, d = row offset
        const int i = m >> 2;
#pragma unroll
        for (int ch = 0; ch < 2; ch++) {
#pragma unroll
            for (int cq = 0; cq < 4; cq++) {
                const int bcol = n0 + ch * 64 + tc * 4 + cq;
                float v0 = acc[rh * 4 + 0][ch * 4 + cq];
                float v1 = acc[rh * 4 + 1][ch * 4 + cq];
                float v2 = acc[rh * 4 + 2][ch * 4 + cq];
                float v3 = acc[rh * 4 + 3][ch * 4 + cq];
                float nrm = sqrtf(v0 * v0 + v1 * v1 + v2 * v2 + v3 * v3);
                float inv = 1.0f / fmaxf(nrm, EPS_N);
                float4 o = make_float4(v0 * inv, v1 * inv, v2 * inv, v3 * inv);
                *(float4*)&g_V[0][(long)i * NCOL + (long)bcol * 4] = o;
            }
        }
    }
}

// ---------------------------------------------------------------------------
// One Kuramoto step: C[i,n] = sum_j Kt[i,j] * Vin[j,n],   n = b*4+d
// v_new = normalize(v_old + (C + omega))   (DT = 1)
// FINAL writes d_out in [B, OUT, D] layout; otherwise ping-pong buffer.
// ---------------------------------------------------------------------------
template <bool FINAL>
__global__ __launch_bounds__(NTHREADS, 2)
void step_kernel(int sIn, const float* __restrict__ omega, float* __restrict__ out) {
    __shared__ float As[BK][BM + 4];    // As[kk][mm] = Kt[(m0+mm)*1024 + j0+kk]
    __shared__ float Bs[BK][BN];        // Bs[kk][nn] = Vin[(j0+kk)*NCOL + n0+nn]

    const float* __restrict__ Vin = g_V[sIn];
    float* __restrict__ Vout = FINAL ? out : g_V[1 - sIn];

    const int m0 = blockIdx.y * BM;     // i rows
    const int n0 = blockIdx.x * BN;     // n cols
    const int tid = threadIdx.x;
    const int tc = tid & 15;
    const int tr = tid >> 4;

    // A tile load (transposed): 2 threads per i row, 4 j each
    const int a_mm = tid >> 1;
    const int a_jq = (tid & 1) * 4;
    // B tile load (direct, coalesced)
    const int b_kk = tid >> 5;
    const int b_nn = (tid & 31) * 4;

    const float* Aptr = g_Kt + (long)(m0 + a_mm) * OUT_SZ + a_jq;
    const float* Bptr = Vin + (long)b_kk * NCOL + n0 + b_nn;

    float acc[8][8];
#pragma unroll
    for (int r = 0; r < 8; r++)
#pragma unroll
        for (int c = 0; c < 8; c++) acc[r][c] = 0.f;

    float4 pa = *(const float4*)(Aptr);
    float4 pb = *(const float4*)(Bptr);

    for (int j0 = 0; j0 < OUT_SZ; j0 += BK) {
        As[a_jq + 0][a_mm] = pa.x;
        As[a_jq + 1][a_mm] = pa.y;
        As[a_jq + 2][a_mm] = pa.z;
        As[a_jq + 3][a_mm] = pa.w;
        *(float4*)&Bs[b_kk][b_nn] = pb;
        __syncthreads();
        if (j0 + BK < OUT_SZ) {
            pa = *(const float4*)(Aptr + (j0 + BK));
            pb = *(const float4*)(Bptr + (long)(j0 + BK) * NCOL);
        }
#pragma unroll
        for (int kk = 0; kk < BK; kk++) {
            float a[8], b[8];
            *(float4*)&a[0] = *(const float4*)&As[kk][tr * 4];
            *(float4*)&a[4] = *(const float4*)&As[kk][64 + tr * 4];
            *(float4*)&b[0] = *(const float4*)&Bs[kk][tc * 4];
            *(float4*)&b[4] = *(const float4*)&Bs[kk][64 + tc * 4];
#pragma unroll
            for (int r = 0; r < 8; r++)
#pragma unroll
                for (int c = 0; c < 8; c++)
                    acc[r][c] = fmaf(a[r], b[c], acc[r][c]);
        }
        __syncthreads();
    }

    // Epilogue: cols are n = b*4+d; normalize groups of 4 consecutive cols.
#pragma unroll
    for (int rh = 0; rh < 2; rh++) {
#pragma unroll
        for (int rq = 0; rq < 4; rq++) {
            const int i = m0 + rh * 64 + tr * 4 + rq;
            const float4 om = *(const float4*)&omega[i * 4];   // omega[i][0..3]
#pragma unroll
            for (int ch = 0; ch < 2; ch++) {
                const int nb = n0 + ch * 64 + tc * 4;          // 4-aligned; b = nb>>2
                const float4 vo = *(const float4*)&Vin[(long)i * NCOL + nb];
                float v0 = vo.x + acc[rh * 4 + rq][ch * 4 + 0] + om.x;
                float v1 = vo.y + acc[rh * 4 + rq][ch * 4 + 1] + om.y;
                float v2 = vo.z + acc[rh * 4 + rq][ch * 4 + 2] + om.z;
                float v3 = vo.w + acc[rh * 4 + rq][ch * 4 + 3] + om.w;
                float nrm = sqrtf(v0 * v0 + v1 * v1 + v2 * v2 + v3 * v3);
                float inv = 1.0f / fmaxf(nrm, EPS_N);
                float4 o = make_float4(v0 * inv, v1 * inv, v2 * inv, v3 * inv);
                if (FINAL) {
                    // out[b][i][d]
                    *(float4*)&out[(long)(nb >> 2) * (OUT_SZ * D_SZ) + (long)i * 4] = o;
                } else {
                    *(float4*)&Vout[(long)i * NCOL + nb] = o;
                }
            }
        }
    }
}

// ---------------------------------------------------------------------------
// Launch
// ---------------------------------------------------------------------------
extern "C" void kernel_launch(void* const* d_in, const int* in_sizes, int n_in,
                              void* d_out, int out_size) {
    const float* x     = (const float*)d_in[0];   // [B, IN]
    const float* W_in  = (const float*)d_in[1];   // [IN, OUT, D]
    const float* omega = (const float*)d_in[2];   // [OUT, D]
    const float* coup  = (const float*)d_in[3];   // [OUT, OUT]
    float* out = (float*)d_out;                   // [B, OUT, D]

    tanh_kernel<<<(OUT_SZ * OUT_SZ) / 256, 256>>>(coup);

    init_kernel<<<dim3(B_SZ / BN, (OUT_SZ * D_SZ) / BM), NTHREADS>>>(x, W_in);

    dim3 sgrid(NCOL / BN, OUT_SZ / BM);
    int s = 0;
    for (int t = 0; t < NSTEPS - 1; t++) {
        step_kernel<false><<<sgrid, NTHREADS>>>(s, omega, out);
        s ^= 1;
    }
    step_kernel<true><<<sgrid, NTHREADS>>>(s, omega, out);
}

// round 2
// speedup vs baseline: 1.0013x; 1.0013x over previous
#include <cuda_runtime.h>
#include <math.h>

// Problem constants
#define B_SZ   8192
#define IN_SZ  1024
#define OUT_SZ 1024
#define D_SZ   4
#define NSTEPS 8
#define NCOL   (B_SZ * D_SZ)      /* 32768 columns of the step GEMM */
#define EPS_N  1e-12f

// GEMM tiling
#define BM 128
#define BN 128
#define BK 8
#define NTHREADS 256

// Ping-pong state buffers: V[s][i][b*4+d]  (OUT-major, D innermost)
__device__ float g_V[2][(long)OUT_SZ * NCOL];   // 2 x 128 MB
__device__ float g_Kt[OUT_SZ * OUT_SZ];         // tanh(coupling)

// ---------------------------------------------------------------------------
// K = tanh(coupling)
// ---------------------------------------------------------------------------
__global__ void tanh_kernel(const float* __restrict__ coup) {
    int i = blockIdx.x * 256 + threadIdx.x;
    g_Kt[i] = tanhf(coup[i]);
}

// ---------------------------------------------------------------------------
// Initial projection: C2[m,b] = sum_k W[k*4096+m] * x[b*1024+k],  m=(i,d)
// Output normalized over d and stored as V[0][i][b*4+d].
// ---------------------------------------------------------------------------
__global__ __launch_bounds__(NTHREADS, 2)
void init_kernel(const float* __restrict__ x, const float* __restrict__ W) {
    __shared__ float As[BK][BM];        // As[kk][mm] = W[(k0+kk)*4096 + m0+mm]
    __shared__ float Bs[BK][BN + 4];    // Bs[kk][bb] = x[(n0+bb)*1024 + k0+kk]

    const int m0 = blockIdx.y * BM;     // (i,d) row block
    const int n0 = blockIdx.x * BN;     // b column block
    const int tid = threadIdx.x;
    const int tc = tid & 15;
    const int tr = tid >> 4;

    // A tile load (direct, coalesced): 256 threads x float4
    const int a_kk = tid >> 5;                  // 0..7
    const int a_mm = (tid & 31) * 4;
    // B tile load (transposed): 2 threads per b row, 4 k each
    const int b_bb = tid >> 1;                  // 0..127
    const int b_kq = (tid & 1) * 4;

    const float* Aptr = W + (long)a_kk * (OUT_SZ * D_SZ) + m0 + a_mm;
    const float* Bptr = x + (long)(n0 + b_bb) * IN_SZ + b_kq;

    float acc[8][8];
#pragma unroll
    for (int r = 0; r < 8; r++)
#pragma unroll
        for (int c = 0; c < 8; c++) acc[r][c] = 0.f;

    float4 pa = *(const float4*)(Aptr);
    float4 pb = *(const float4*)(Bptr);

    for (int k0 = 0; k0 < IN_SZ; k0 += BK) {
        *(float4*)&As[a_kk][a_mm] = pa;
        Bs[b_kq + 0][b_bb] = pb.x;
        Bs[b_kq + 1][b_bb] = pb.y;
        Bs[b_kq + 2][b_bb] = pb.z;
        Bs[b_kq + 3][b_bb] = pb.w;
        __syncthreads();
        if (k0 + BK < IN_SZ) {
            pa = *(const float4*)(Aptr + (long)(k0 + BK) * (OUT_SZ * D_SZ));
            pb = *(const float4*)(Bptr + (k0 + BK));
        }
#pragma unroll
        for (int kk = 0; kk < BK; kk++) {
            float a[8], b[8];
            *(float4*)&a[0] = *(const float4*)&As[kk][tr * 4];
            *(float4*)&a[4] = *(const float4*)&As[kk][64 + tr * 4];
            *(float4*)&b[0] = *(const float4*)&Bs[kk][tc * 4];
            *(float4*)&b[4] = *(const float4*)&Bs[kk][64 + tc * 4];
#pragma unroll
            for (int r = 0; r < 8; r++)
#pragma unroll
                for (int c = 0; c < 8; c++)
                    acc[r][c] = fmaf(a[r], b[c], acc[r][c]);
        }
        __syncthreads();
    }

    // Epilogue: rows are (i,d); normalize groups of 4 rows (fixed i, d=0..3).
#pragma unroll
    for (int rh = 0; rh < 2; rh++) {
        const int m = m0 + rh * 64 + tr * 4;    // 4-aligned -> i = m>>2, d = row offset
        const int i = m >> 2;
#pragma unroll
        for (int ch = 0; ch < 2; ch++) {
#pragma unroll
            for (int cq = 0; cq < 4; cq++) {
                const int bcol = n0 + ch * 64 + tc * 4 + cq;
                float v0 = acc[rh * 4 + 0][ch * 4 + cq];
                float v1 = acc[rh * 4 + 1][ch * 4 + cq];
                float v2 = acc[rh * 4 + 2][ch * 4 + cq];
                float v3 = acc[rh * 4 + 3][ch * 4 + cq];
                float nrm = sqrtf(v0 * v0 + v1 * v1 + v2 * v2 + v3 * v3);
                float inv = 1.0f / fmaxf(nrm, EPS_N);
                float4 o = make_float4(v0 * inv, v1 * inv, v2 * inv, v3 * inv);
                *(float4*)&g_V[0][(long)i * NCOL + (long)bcol * 4] = o;
            }
        }
    }
}

// ---------------------------------------------------------------------------
// One Kuramoto step: C[i,n] = sum_j Kt[i,j] * Vin[j,n],   n = b*4+d
// v_new = normalize(v_old + (C + omega))   (DT = 1)
// FINAL writes d_out in [B, OUT, D] layout; otherwise ping-pong buffer.
// ---------------------------------------------------------------------------
template <bool FINAL>
__global__ __launch_bounds__(NTHREADS, 2)
void step_kernel(int sIn, const float* __restrict__ omega, float* __restrict__ out) {
    __shared__ float As[BK][BM + 4];    // As[kk][mm] = Kt[(m0+mm)*1024 + j0+kk]
    __shared__ float Bs[BK][BN];        // Bs[kk][nn] = Vin[(j0+kk)*NCOL + n0+nn]

    const float* __restrict__ Vin = g_V[sIn];
    float* __restrict__ Vout = FINAL ? out : g_V[1 - sIn];

    const int m0 = blockIdx.y * BM;     // i rows
    const int n0 = blockIdx.x * BN;     // n cols
    const int tid = threadIdx.x;
    const int tc = tid & 15;
    const int tr = tid >> 4;

    // A tile load (transposed): 2 threads per i row, 4 j each
    const int a_mm = tid >> 1;
    const int a_jq = (tid & 1) * 4;
    // B tile load (direct, coalesced)
    const int b_kk = tid >> 5;
    const int b_nn = (tid & 31) * 4;

    const float* Aptr = g_Kt + (long)(m0 + a_mm) * OUT_SZ + a_jq;
    const float* Bptr = Vin + (long)b_kk * NCOL + n0 + b_nn;

    float acc[8][8];
#pragma unroll
    for (int r = 0; r < 8; r++)
#pragma unroll
        for (int c = 0; c < 8; c++) acc[r][c] = 0.f;

    float4 pa = *(const float4*)(Aptr);
    float4 pb = *(const float4*)(Bptr);

    for (int j0 = 0; j0 < OUT_SZ; j0 += BK) {
        As[a_jq + 0][a_mm] = pa.x;
        As[a_jq + 1][a_mm] = pa.y;
        As[a_jq + 2][a_mm] = pa.z;
        As[a_jq + 3][a_mm] = pa.w;
        *(float4*)&Bs[b_kk][b_nn] = pb;
        __syncthreads();
        if (j0 + BK < OUT_SZ) {
            pa = *(const float4*)(Aptr + (j0 + BK));
            pb = *(const float4*)(Bptr + (long)(j0 + BK) * NCOL);
        }
#pragma unroll
        for (int kk = 0; kk < BK; kk++) {
            float a[8], b[8];
            *(float4*)&a[0] = *(const float4*)&As[kk][tr * 4];
            *(float4*)&a[4] = *(const float4*)&As[kk][64 + tr * 4];
            *(float4*)&b[0] = *(const float4*)&Bs[kk][tc * 4];
            *(float4*)&b[4] = *(const float4*)&Bs[kk][64 + tc * 4];
#pragma unroll
            for (int r = 0; r < 8; r++)
#pragma unroll
                for (int c = 0; c < 8; c++)
                    acc[r][c] = fmaf(a[r], b[c], acc[r][c]);
        }
        __syncthreads();
    }

    // Epilogue: cols are n = b*4+d; normalize groups of 4 consecutive cols.
#pragma unroll
    for (int rh = 0; rh < 2; rh++) {
#pragma unroll
        for (int rq = 0; rq < 4; rq++) {
            const int i = m0 + rh * 64 + tr * 4 + rq;
            const float4 om = *(const float4*)&omega[i * 4];   // omega[i][0..3]
#pragma unroll
            for (int ch = 0; ch < 2; ch++) {
                const int nb = n0 + ch * 64 + tc * 4;          // 4-aligned; b = nb>>2
                const float4 vo = *(const float4*)&Vin[(long)i * NCOL + nb];
                float v0 = vo.x + acc[rh * 4 + rq][ch * 4 + 0] + om.x;
                float v1 = vo.y + acc[rh * 4 + rq][ch * 4 + 1] + om.y;
                float v2 = vo.z + acc[rh * 4 + rq][ch * 4 + 2] + om.z;
                float v3 = vo.w + acc[rh * 4 + rq][ch * 4 + 3] + om.w;
                float nrm = sqrtf(v0 * v0 + v1 * v1 + v2 * v2 + v3 * v3);
                float inv = 1.0f / fmaxf(nrm, EPS_N);
                float4 o = make_float4(v0 * inv, v1 * inv, v2 * inv, v3 * inv);
                if (FINAL) {
                    // out[b][i][d]
                    *(float4*)&out[(long)(nb >> 2) * (OUT_SZ * D_SZ) + (long)i * 4] = o;
                } else {
                    *(float4*)&Vout[(long)i * NCOL + nb] = o;
                }
            }
        }
    }
}

// ---------------------------------------------------------------------------
// Launch
// ---------------------------------------------------------------------------
extern "C" void kernel_launch(void* const* d_in, const int* in_sizes, int n_in,
                              void* d_out, int out_size) {
    const float* x     = (const float*)d_in[0];   // [B, IN]
    const float* W_in  = (const float*)d_in[1];   // [IN, OUT, D]
    const float* omega = (const float*)d_in[2];   // [OUT, D]
    const float* coup  = (const float*)d_in[3];   // [OUT, OUT]
    float* out = (float*)d_out;                   // [B, OUT, D]

    tanh_kernel<<<(OUT_SZ * OUT_SZ) / 256, 256>>>(coup);

    init_kernel<<<dim3(B_SZ / BN, (OUT_SZ * D_SZ) / BM), NTHREADS>>>(x, W_in);

    dim3 sgrid(NCOL / BN, OUT_SZ / BM);
    int s = 0;
    for (int t = 0; t < NSTEPS - 1; t++) {
        step_kernel<false><<<sgrid, NTHREADS>>>(s, omega, out);
        s ^= 1;
    }
    step_kernel<true><<<sgrid, NTHREADS>>>(s, omega, out);
}

// round 10
// speedup vs baseline: 1.2089x; 1.2073x over previous
#include <cuda_runtime.h>
#include <cuda_fp16.h>
#include <math.h>
#include <stdint.h>

// ---------------- problem constants ----------------
#define B_SZ   8192
#define OUT_SZ 1024
#define IN_SZ  1024
#define D_SZ   4
#define NSTEPS 8
#define NROW   (B_SZ * D_SZ)          /* 32768 state rows n = b*4+d */
#define MTOT_I (OUT_SZ * D_SZ)        /* 4096 init-GEMM M */
#define EPS_N  1e-12f

// ---------------- tiling ----------------
#define BT   128                      /* CTA tile: 128 x 128 */
#define KCH  32                       /* k per chunk */
#define NCHUNK 32                     /* K = 1024 */
#define NTHR 256
#define STAGES 3
#define STG_BYTES 32768               /* A 16KB + B 16KB per stage */
#define B_OFF 16384
#define DSMEM (STAGES * STG_BYTES + 1024)

#define SWZ(o) ((o) ^ (((o) >> 3) & 0x70))

// ---------------- device buffers (split fp16) ----------------
__device__ __half g_Kth[OUT_SZ * OUT_SZ];               // tanh(coupling)+I, [i][j]
__device__ __half g_Ktl[OUT_SZ * OUT_SZ];
__device__ __half g_Wth[(size_t)MTOT_I * IN_SZ];        // W transposed [m=(o,d)][k]
__device__ __half g_Wtl[(size_t)MTOT_I * IN_SZ];
__device__ __half g_xh[(size_t)B_SZ * IN_SZ];           // x [b][k]
__device__ __half g_xl[(size_t)B_SZ * IN_SZ];
__device__ __half g_Vh[2][(size_t)NROW * OUT_SZ];       // state [n][j]
__device__ __half g_Vl[2][(size_t)NROW * OUT_SZ];

// ---------------- PTX helpers (baseline, sm_80-era) ----------------
__device__ __forceinline__ uint32_t smem_u32(const void* p) {
    uint32_t a;
    asm("{ .reg .u64 t; cvta.to.shared.u64 t, %1; cvt.u32.u64 %0, t; }" : "=r"(a) : "l"(p));
    return a;
}
__device__ __forceinline__ void cpasync16(uint32_t dst, const void* src) {
    asm volatile("cp.async.cg.shared.global [%0], [%1], 16;" :: "r"(dst), "l"(src));
}
#define CP_COMMIT() asm volatile("cp.async.commit_group;" ::: "memory")
#define CP_WAIT1()  asm volatile("cp.async.wait_group 1;" ::: "memory")

__device__ __forceinline__ void ldsm4(uint32_t* r, uint32_t addr) {
    asm volatile("ldmatrix.sync.aligned.m8n8.x4.shared.b16 {%0,%1,%2,%3}, [%4];"
                 : "=r"(r[0]), "=r"(r[1]), "=r"(r[2]), "=r"(r[3]) : "r"(addr));
}
__device__ __forceinline__ void mma16816(float* d, const uint32_t* a, const uint32_t* b) {
    asm volatile(
        "mma.sync.aligned.m16n8k16.row.col.f32.f16.f16.f32 "
        "{%0,%1,%2,%3}, {%4,%5,%6,%7}, {%8,%9}, {%0,%1,%2,%3};"
        : "+f"(d[0]), "+f"(d[1]), "+f"(d[2]), "+f"(d[3])
        : "r"(a[0]), "r"(a[1]), "r"(a[2]), "r"(a[3]), "r"(b[0]), "r"(b[1]));
}

// ---------------------------------------------------------------------------
// Prep kernels: build split-fp16 operands.
// ---------------------------------------------------------------------------
__global__ void prep_kt(const float* __restrict__ coup) {
    int idx = blockIdx.x * 256 + threadIdx.x;
    int i = idx >> 10, j = idx & 1023;
    float t = tanhf(coup[idx]) + (i == j ? 1.0f : 0.0f);
    __half h = __float2half(t);
    g_Kth[idx] = h;
    g_Ktl[idx] = __float2half(t - __half2float(h));
}

__global__ void prep_x(const float* __restrict__ x) {
    size_t idx = (size_t)blockIdx.x * 256 + threadIdx.x;
    float v = x[idx];
    __half h = __float2half(v);
    g_xh[idx] = h;
    g_xl[idx] = __float2half(v - __half2float(h));
}

// W[k][m] (1024 x 4096 row-major) -> Wt[m][k] split
__global__ void prep_wt(const float* __restrict__ W) {
    __shared__ float t[32][33];
    int tx = threadIdx.x & 31, ty = threadIdx.x >> 5;   // ty 0..7
    int m0 = blockIdx.x * 32, k0 = blockIdx.y * 32;
#pragma unroll
    for (int i = 0; i < 32; i += 8)
        t[ty + i][tx] = W[(size_t)(k0 + ty + i) * MTOT_I + m0 + tx];
    __syncthreads();
#pragma unroll
    for (int i = 0; i < 32; i += 8) {
        float v = t[tx][ty + i];
        __half h = __float2half(v);
        size_t off = (size_t)(m0 + ty + i) * IN_SZ + k0 + tx;
        g_Wth[off] = h;
        g_Wtl[off] = __float2half(v - __half2float(h));
    }
}

// ---------------------------------------------------------------------------
// Fused split-fp16 GEMM + normalize epilogue.
// C[m][n] = sum_k A[m][k]*B[n][k]  (3-pass split accumulate, fp32)
// MODE 0: init   A=Wt[m=(o,d)][k], B=x[b][k];  write V0[(b*4+d)][o] (norm over m-quads)
// MODE 1: step   A=Vt[n][j],       B=K'[i][j]; write Vout[n][i]     (norm over n-quads)
// MODE 2: step final -> write d_out[b][i][d] fp32
// ---------------------------------------------------------------------------
template <int MODE>
__global__ __launch_bounds__(NTHR, 1)
void gemm_f16(int sIn, const float* __restrict__ omega, float* __restrict__ out) {
    extern __shared__ char dsm_raw[];
    char* dsm = (char*)(((uintptr_t)dsm_raw + 1023) & ~(uintptr_t)1023);
    const uint32_t smemBase = smem_u32(dsm);

    const __half* __restrict__ Ah;
    const __half* __restrict__ Al;
    const __half* __restrict__ Bh;
    const __half* __restrict__ Bl;
    __half* __restrict__ Voh;
    __half* __restrict__ Vol;
    if (MODE == 0) {
        Ah = g_Wth; Al = g_Wtl; Bh = g_xh; Bl = g_xl;
        Voh = g_Vh[0]; Vol = g_Vl[0];
    } else {
        Ah = g_Vh[sIn]; Al = g_Vl[sIn]; Bh = g_Kth; Bl = g_Ktl;
        Voh = g_Vh[sIn ^ 1]; Vol = g_Vl[sIn ^ 1];
    }

    const int tid = threadIdx.x;
    const int lane = tid & 31;
    const int w = tid >> 5;
    const int wm = w & 3;        // 4 m-warps of 32 rows
    const int wn = w >> 2;       // 2 n-warps of 64 cols
    const int m0 = blockIdx.y * BT;
    const int n0 = blockIdx.x * BT;

    // cp.async per-thread assignments (4 units of 16B for A, 4 for B)
    int cp_r[4], cp_c[4];
    uint32_t cp_dA[4], cp_dB[4];
#pragma unroll
    for (int i = 0; i < 4; i++) {
        int u = tid + i * 256;
        cp_r[i] = u >> 3;
        cp_c[i] = u & 7;
        uint32_t o = SWZ((uint32_t)(cp_r[i] * 128 + cp_c[i] * 16));
        cp_dA[i] = smemBase + o;
        cp_dB[i] = smemBase + B_OFF + o;
    }

    // ldmatrix per-thread UNSWIZZLED base offsets; swizzle applied per-access
    // (SWZ(base)+k != SWZ(base+k) because the XOR mask hits bits 5:6).
    uint32_t aBase[2], bBase[4];
#pragma unroll
    for (int mi = 0; mi < 2; mi++) {
        int r = wm * 32 + mi * 16 + (lane & 7) + ((lane >> 3) & 1) * 8;
        int cc = (lane >> 4);
        aBase[mi] = (uint32_t)(r * 128 + cc * 16);
    }
#pragma unroll
    for (int nj = 0; nj < 4; nj++) {
        int r = wn * 64 + nj * 16 + (lane & 7) + ((lane >> 4) << 3);
        int cc = (lane >> 3) & 1;
        bBase[nj] = (uint32_t)(r * 128 + cc * 16);
    }

    float acc[2][8][4];
#pragma unroll
    for (int a = 0; a < 2; a++)
#pragma unroll
        for (int b = 0; b < 8; b++)
#pragma unroll
            for (int c = 0; c < 4; c++) acc[a][b][c] = 0.f;

    // chunk copy: A rows m0.., B rows n0.., 16B units; c<4 -> hi half, else lo
    auto copy_chunk = [&](int stage, int k0) {
        uint32_t sb = (uint32_t)(stage * STG_BYTES);
#pragma unroll
        for (int i = 0; i < 4; i++) {
            const __half* src = (cp_c[i] < 4 ? Ah : Al) +
                (size_t)(m0 + cp_r[i]) * 1024 + k0 + (cp_c[i] & 3) * 8;
            cpasync16(cp_dA[i] + sb, src);
        }
#pragma unroll
        for (int i = 0; i < 4; i++) {
            const __half* src = (cp_c[i] < 4 ? Bh : Bl) +
                (size_t)(n0 + cp_r[i]) * 1024 + k0 + (cp_c[i] & 3) * 8;
            cpasync16(cp_dB[i] + sb, src);
        }
    };

    copy_chunk(0, 0);  CP_COMMIT();
    copy_chunk(1, 32); CP_COMMIT();

    for (int c = 0; c < NCHUNK; c++) {
        CP_WAIT1();
        __syncthreads();
        const uint32_t stg = smemBase + (uint32_t)((c % STAGES) * STG_BYTES);
        if (c + 2 < NCHUNK) copy_chunk((c + 2) % STAGES, (c + 2) * KCH);
        CP_COMMIT();

#pragma unroll
        for (int s = 0; s < 2; s++) {
            uint32_t ah[2][4], al[2][4], bh[4][4], bl[4][4];
            const uint32_t ks = (uint32_t)(s * 32);
#pragma unroll
            for (int mi = 0; mi < 2; mi++) {
                ldsm4(ah[mi], stg + SWZ(aBase[mi] + ks));
                ldsm4(al[mi], stg + SWZ(aBase[mi] + ks + 64));
            }
#pragma unroll
            for (int nj = 0; nj < 4; nj++) {
                ldsm4(bh[nj], stg + B_OFF + SWZ(bBase[nj] + ks));
                ldsm4(bl[nj], stg + B_OFF + SWZ(bBase[nj] + ks + 64));
            }
            // pass 1: ah * bh
#pragma unroll
            for (int mi = 0; mi < 2; mi++)
#pragma unroll
                for (int nj = 0; nj < 4; nj++) {
                    mma16816(acc[mi][2 * nj + 0], ah[mi], &bh[nj][0]);
                    mma16816(acc[mi][2 * nj + 1], ah[mi], &bh[nj][2]);
                }
            // pass 2: ah * bl
#pragma unroll
            for (int mi = 0; mi < 2; mi++)
#pragma unroll
                for (int nj = 0; nj < 4; nj++) {
                    mma16816(acc[mi][2 * nj + 0], ah[mi], &bl[nj][0]);
                    mma16816(acc[mi][2 * nj + 1], ah[mi], &bl[nj][2]);
                }
            // pass 3: al * bh
#pragma unroll
            for (int mi = 0; mi < 2; mi++)
#pragma unroll
                for (int nj = 0; nj < 4; nj++) {
                    mma16816(acc[mi][2 * nj + 0], al[mi], &bh[nj][0]);
                    mma16816(acc[mi][2 * nj + 1], al[mi], &bh[nj][2]);
                }
        }
    }

    // ---------------- epilogue ----------------
    if (MODE == 0) {
        // rows m=(o,d), cols b. Normalize over m-quads: lanes {l, l^4, l^8}.
#pragma unroll
        for (int mi = 0; mi < 2; mi++) {
            const int mrow = m0 + wm * 32 + mi * 16 + (lane >> 2);
#pragma unroll
            for (int fi = 0; fi < 8; fi++) {
                const int bcol = n0 + wn * 64 + fi * 8 + (lane & 3) * 2;
#pragma unroll
                for (int h = 0; h < 2; h++) {
                    const int m = mrow + h * 8;
                    const int o = m >> 2, d = m & 3;
                    float v0 = acc[mi][fi][h * 2 + 0];
                    float v1 = acc[mi][fi][h * 2 + 1];
                    float s0 = v0 * v0, s1 = v1 * v1;
                    s0 += __shfl_xor_sync(~0u, s0, 4); s0 += __shfl_xor_sync(~0u, s0, 8);
                    s1 += __shfl_xor_sync(~0u, s1, 4); s1 += __shfl_xor_sync(~0u, s1, 8);
                    v0 *= 1.f / fmaxf(sqrtf(s0), EPS_N);
                    v1 *= 1.f / fmaxf(sqrtf(s1), EPS_N);
                    size_t p0 = (size_t)(bcol * 4 + d) * 1024 + o;
                    size_t p1 = (size_t)((bcol + 1) * 4 + d) * 1024 + o;
                    __half h0 = __float2half(v0), h1 = __float2half(v1);
                    Voh[p0] = h0; Vol[p0] = __float2half(v0 - __half2float(h0));
                    Voh[p1] = h1; Vol[p1] = __float2half(v1 - __half2float(h1));
                }
            }
        }
    } else {
        // rows n=(b,d), cols i. Normalize over n-quads: lanes {l, l^4, l^8}.
#pragma unroll
        for (int mi = 0; mi < 2; mi++) {
            const int nrow = m0 + wm * 32 + mi * 16 + (lane >> 2);
            const int d = nrow & 3;
#pragma unroll
            for (int fi = 0; fi < 8; fi++) {
                const int icol = n0 + wn * 64 + fi * 8 + (lane & 3) * 2;
                const float om0 = omega[icol * 4 + d];
                const float om1 = omega[icol * 4 + 4 + d];
#pragma unroll
                for (int h = 0; h < 2; h++) {
                    const int n = nrow + h * 8;
                    float v0 = acc[mi][fi][h * 2 + 0] + om0;
                    float v1 = acc[mi][fi][h * 2 + 1] + om1;
                    float s0 = v0 * v0, s1 = v1 * v1;
                    s0 += __shfl_xor_sync(~0u, s0, 4); s0 += __shfl_xor_sync(~0u, s0, 8);
                    s1 += __shfl_xor_sync(~0u, s1, 4); s1 += __shfl_xor_sync(~0u, s1, 8);
                    v0 *= 1.f / fmaxf(sqrtf(s0), EPS_N);
                    v1 *= 1.f / fmaxf(sqrtf(s1), EPS_N);
                    if (MODE == 2) {
                        out[(size_t)(n >> 2) * 4096 + icol * 4 + d] = v0;
                        out[(size_t)(n >> 2) * 4096 + (icol + 1) * 4 + d] = v1;
                    } else {
                        __half h0 = __float2half(v0), h1 = __float2half(v1);
                        __half2 hh; hh.x = h0; hh.y = h1;
                        *(__half2*)(Voh + (size_t)n * 1024 + icol) = hh;
                        __half2 ll;
                        ll.x = __float2half(v0 - __half2float(h0));
                        ll.y = __float2half(v1 - __half2float(h1));
                        *(__half2*)(Vol + (size_t)n * 1024 + icol) = ll;
                    }
                }
            }
        }
    }
}

// ---------------------------------------------------------------------------
// Launch
// ---------------------------------------------------------------------------
extern "C" void kernel_launch(void* const* d_in, const int* in_sizes, int n_in,
                              void* d_out, int out_size) {
    const float* x     = (const float*)d_in[0];   // [B, IN]
    const float* W_in  = (const float*)d_in[1];   // [IN, OUT, D]
    const float* omega = (const float*)d_in[2];   // [OUT, D]
    const float* coup  = (const float*)d_in[3];   // [OUT, OUT]
    float* out = (float*)d_out;                   // [B, OUT, D]

    cudaFuncSetAttribute(gemm_f16<0>, cudaFuncAttributeMaxDynamicSharedMemorySize, DSMEM);
    cudaFuncSetAttribute(gemm_f16<1>, cudaFuncAttributeMaxDynamicSharedMemorySize, DSMEM);
    cudaFuncSetAttribute(gemm_f16<2>, cudaFuncAttributeMaxDynamicSharedMemorySize, DSMEM);

    prep_kt<<<(OUT_SZ * OUT_SZ) / 256, 256>>>(coup);
    prep_x<<<(B_SZ * IN_SZ) / 256, 256>>>(x);
    prep_wt<<<dim3(MTOT_I / 32, IN_SZ / 32), 256>>>(W_in);

    // init: M = 4096 (m=(o,d)), N = 8192 (b)
    gemm_f16<0><<<dim3(B_SZ / BT, MTOT_I / BT), NTHR, DSMEM>>>(0, omega, out);

    // steps: M = 32768 (n), N = 1024 (i); x-dim (i blocks) fastest -> A-tile L2 reuse
    dim3 sgrid(OUT_SZ / BT, NROW / BT);
    int s = 0;
    for (int t = 0; t < NSTEPS - 1; t++) {
        gemm_f16<1><<<sgrid, NTHR, DSMEM>>>(s, omega, out);
        s ^= 1;
    }
    gemm_f16<2><<<sgrid, NTHR, DSMEM>>>(s, omega, out);
}

// round 11
// speedup vs baseline: 2.1877x; 1.8097x over previous
#include <cuda_runtime.h>
#include <cuda_fp16.h>
#include <math.h>
#include <stdint.h>

// ---------------- problem constants ----------------
#define B_SZ   8192
#define OUT_SZ 1024
#define IN_SZ  1024
#define D_SZ   4
#define NSTEPS 8
#define NROW   (B_SZ * D_SZ)          /* 32768 state rows n = b*4+d */
#define MTOT_I (OUT_SZ * D_SZ)        /* 4096 init-GEMM M */
#define EPS_N  1e-12f

// ---------------- tiling ----------------
#define BTM  128                      /* CTA tile M */
#define BTN  256                      /* CTA tile N */
#define KCH  32                       /* k per chunk */
#define NCHUNK 32                     /* K = 1024 */
#define NTHR 512                      /* 16 warps: 4 (m) x 4 (n), warp tile 32x64 */
#define STAGES 3
#define STG_BYTES 49152               /* A 16KB + B 32KB per stage */
#define B_OFF 16384
#define DSMEM (STAGES * STG_BYTES + 1024)

#define SWZ(o) ((o) ^ (((o) >> 3) & 0x70))

// ---------------- device buffers (split fp16) ----------------
__device__ __half g_Kth[OUT_SZ * OUT_SZ];               // tanh(coupling)+I, [i][j]
__device__ __half g_Ktl[OUT_SZ * OUT_SZ];
__device__ __half g_Wth[(size_t)MTOT_I * IN_SZ];        // W transposed [m=(o,d)][k]
__device__ __half g_Wtl[(size_t)MTOT_I * IN_SZ];
__device__ __half g_xh[(size_t)B_SZ * IN_SZ];           // x [b][k]
__device__ __half g_xl[(size_t)B_SZ * IN_SZ];
__device__ __half g_Vh[2][(size_t)NROW * OUT_SZ];       // state [n][j]
__device__ __half g_Vl[2][(size_t)NROW * OUT_SZ];

// ---------------- PTX helpers (baseline, sm_80-era) ----------------
__device__ __forceinline__ uint32_t smem_u32(const void* p) {
    uint32_t a;
    asm("{ .reg .u64 t; cvta.to.shared.u64 t, %1; cvt.u32.u64 %0, t; }" : "=r"(a) : "l"(p));
    return a;
}
__device__ __forceinline__ void cpasync16(uint32_t dst, const void* src) {
    asm volatile("cp.async.cg.shared.global [%0], [%1], 16;" :: "r"(dst), "l"(src));
}
#define CP_COMMIT() asm volatile("cp.async.commit_group;" ::: "memory")
#define CP_WAIT1()  asm volatile("cp.async.wait_group 1;" ::: "memory")

__device__ __forceinline__ void ldsm4(uint32_t* r, uint32_t addr) {
    asm volatile("ldmatrix.sync.aligned.m8n8.x4.shared.b16 {%0,%1,%2,%3}, [%4];"
                 : "=r"(r[0]), "=r"(r[1]), "=r"(r[2]), "=r"(r[3]) : "r"(addr));
}
__device__ __forceinline__ void mma16816(float* d, const uint32_t* a, const uint32_t* b) {
    asm volatile(
        "mma.sync.aligned.m16n8k16.row.col.f32.f16.f16.f32 "
        "{%0,%1,%2,%3}, {%4,%5,%6,%7}, {%8,%9}, {%0,%1,%2,%3};"
        : "+f"(d[0]), "+f"(d[1]), "+f"(d[2]), "+f"(d[3])
        : "r"(a[0]), "r"(a[1]), "r"(a[2]), "r"(a[3]), "r"(b[0]), "r"(b[1]));
}

// ---------------------------------------------------------------------------
// Prep kernels: build split-fp16 operands.
// ---------------------------------------------------------------------------
__global__ void prep_kt(const float* __restrict__ coup) {
    int idx = blockIdx.x * 256 + threadIdx.x;
    int i = idx >> 10, j = idx & 1023;
    float t = tanhf(coup[idx]) + (i == j ? 1.0f : 0.0f);
    __half h = __float2half(t);
    g_Kth[idx] = h;
    g_Ktl[idx] = __float2half(t - __half2float(h));
}

__global__ void prep_x(const float* __restrict__ x) {
    size_t idx = (size_t)blockIdx.x * 256 + threadIdx.x;
    float v = x[idx];
    __half h = __float2half(v);
    g_xh[idx] = h;
    g_xl[idx] = __float2half(v - __half2float(h));
}

// W[k][m] (1024 x 4096 row-major) -> Wt[m][k] split
__global__ void prep_wt(const float* __restrict__ W) {
    __shared__ float t[32][33];
    int tx = threadIdx.x & 31, ty = threadIdx.x >> 5;   // ty 0..7
    int m0 = blockIdx.x * 32, k0 = blockIdx.y * 32;
#pragma unroll
    for (int i = 0; i < 32; i += 8)
        t[ty + i][tx] = W[(size_t)(k0 + ty + i) * MTOT_I + m0 + tx];
    __syncthreads();
#pragma unroll
    for (int i = 0; i < 32; i += 8) {
        float v = t[tx][ty + i];
        __half h = __float2half(v);
        size_t off = (size_t)(m0 + ty + i) * IN_SZ + k0 + tx;
        g_Wth[off] = h;
        g_Wtl[off] = __float2half(v - __half2float(h));
    }
}

// ---------------------------------------------------------------------------
// Fused split-fp16 GEMM + normalize epilogue.
// C[m][n] = sum_k A[m][k]*B[n][k]  (3-pass split accumulate, fp32)
// MODE 0: init   A=Wt[m=(o,d)][k], B=x[b][k];  write V0[(b*4+d)][o] (norm over m-quads)
// MODE 1: step   A=Vt[n][j],       B=K'[i][j]; write Vout[n][i]     (norm over n-quads)
// MODE 2: step final -> write d_out[b][i][d] fp32
// ---------------------------------------------------------------------------
template <int MODE>
__global__ __launch_bounds__(NTHR, 1)
void gemm_f16(int sIn, const float* __restrict__ omega, float* __restrict__ out) {
    extern __shared__ char dsm_raw[];
    char* dsm = (char*)(((uintptr_t)dsm_raw + 1023) & ~(uintptr_t)1023);
    const uint32_t smemBase = smem_u32(dsm);

    const __half* __restrict__ Ah;
    const __half* __restrict__ Al;
    const __half* __restrict__ Bh;
    const __half* __restrict__ Bl;
    __half* __restrict__ Voh;
    __half* __restrict__ Vol;
    if (MODE == 0) {
        Ah = g_Wth; Al = g_Wtl; Bh = g_xh; Bl = g_xl;
        Voh = g_Vh[0]; Vol = g_Vl[0];
    } else {
        Ah = g_Vh[sIn]; Al = g_Vl[sIn]; Bh = g_Kth; Bl = g_Ktl;
        Voh = g_Vh[sIn ^ 1]; Vol = g_Vl[sIn ^ 1];
    }

    const int tid = threadIdx.x;
    const int lane = tid & 31;
    const int w = tid >> 5;
    const int wm = w & 3;        // 4 m-warps of 32 rows
    const int wn = w >> 2;       // 4 n-warps of 64 cols
    const int m0 = blockIdx.y * BTM;
    const int n0 = blockIdx.x * BTN;

    // cp.async per-thread assignments: A 2x16B, B 4x16B per thread per stage
    int aR[2], aC[2], bR[4], bC[4];
    uint32_t aD[2], bD[4];
#pragma unroll
    for (int i = 0; i < 2; i++) {
        int u = tid + i * NTHR;            // 0..1023
        aR[i] = u >> 3; aC[i] = u & 7;
        aD[i] = smemBase + SWZ((uint32_t)(aR[i] * 128 + aC[i] * 16));
    }
#pragma unroll
    for (int i = 0; i < 4; i++) {
        int u = tid + i * NTHR;            // 0..2047
        bR[i] = u >> 3; bC[i] = u & 7;
        bD[i] = smemBase + B_OFF + SWZ((uint32_t)(bR[i] * 128 + bC[i] * 16));
    }

    // ldmatrix per-thread UNSWIZZLED base offsets; swizzle applied per access.
    uint32_t aBase[2], bBase[4];
#pragma unroll
    for (int mi = 0; mi < 2; mi++) {
        int r = wm * 32 + mi * 16 + (lane & 7) + ((lane >> 3) & 1) * 8;
        int cc = (lane >> 4);
        aBase[mi] = (uint32_t)(r * 128 + cc * 16);
    }
#pragma unroll
    for (int nj = 0; nj < 4; nj++) {
        int r = wn * 64 + nj * 16 + (lane & 7) + ((lane >> 4) << 3);
        int cc = (lane >> 3) & 1;
        bBase[nj] = (uint32_t)(r * 128 + cc * 16);
    }

    float acc[2][8][4];
#pragma unroll
    for (int a = 0; a < 2; a++)
#pragma unroll
        for (int b = 0; b < 8; b++)
#pragma unroll
            for (int c = 0; c < 4; c++) acc[a][b][c] = 0.f;

    // chunk copy; per 128B row: cols 0-3 hi half, 4-7 lo half of k-chunk
    auto copy_chunk = [&](int stage, int k0) {
        uint32_t sb = (uint32_t)(stage * STG_BYTES);
#pragma unroll
        for (int i = 0; i < 2; i++) {
            const __half* src = (aC[i] < 4 ? Ah : Al) +
                (size_t)(m0 + aR[i]) * 1024 + k0 + (aC[i] & 3) * 8;
            cpasync16(aD[i] + sb, src);
        }
#pragma unroll
        for (int i = 0; i < 4; i++) {
            const __half* src = (bC[i] < 4 ? Bh : Bl) +
                (size_t)(n0 + bR[i]) * 1024 + k0 + (bC[i] & 3) * 8;
            cpasync16(bD[i] + sb, src);
        }
    };

    copy_chunk(0, 0);  CP_COMMIT();
    copy_chunk(1, 32); CP_COMMIT();

    for (int c = 0; c < NCHUNK; c++) {
        CP_WAIT1();
        __syncthreads();
        const uint32_t stg = smemBase + (uint32_t)((c % STAGES) * STG_BYTES);
        if (c + 2 < NCHUNK) copy_chunk((c + 2) % STAGES, (c + 2) * KCH);
        CP_COMMIT();

#pragma unroll
        for (int s = 0; s < 2; s++) {
            const uint32_t ks = (uint32_t)(s * 32);
            uint32_t ah[2][4], al[2][4];
#pragma unroll
            for (int mi = 0; mi < 2; mi++) {
                ldsm4(ah[mi], stg + SWZ(aBase[mi] + ks));
                ldsm4(al[mi], stg + SWZ(aBase[mi] + ks + 64));
            }
            // per-nj B fragments: only 8 B regs live at a time (reg pressure)
#pragma unroll
            for (int nj = 0; nj < 4; nj++) {
                uint32_t bh[4], bl[4];
                ldsm4(bh, stg + B_OFF + SWZ(bBase[nj] + ks));
                ldsm4(bl, stg + B_OFF + SWZ(bBase[nj] + ks + 64));
#pragma unroll
                for (int mi = 0; mi < 2; mi++) {
                    mma16816(acc[mi][2 * nj + 0], ah[mi], &bh[0]);
                    mma16816(acc[mi][2 * nj + 1], ah[mi], &bh[2]);
                    mma16816(acc[mi][2 * nj + 0], ah[mi], &bl[0]);
                    mma16816(acc[mi][2 * nj + 1], ah[mi], &bl[2]);
                    mma16816(acc[mi][2 * nj + 0], al[mi], &bh[0]);
                    mma16816(acc[mi][2 * nj + 1], al[mi], &bh[2]);
                }
            }
        }
    }

    // ---------------- epilogue ----------------
    if (MODE == 0) {
        // rows m=(o,d), cols b. Normalize over m-quads: lanes {l, l^4, l^8}.
#pragma unroll
        for (int mi = 0; mi < 2; mi++) {
            const int mrow = m0 + wm * 32 + mi * 16 + (lane >> 2);
#pragma unroll
            for (int fi = 0; fi < 8; fi++) {
                const int bcol = n0 + wn * 64 + fi * 8 + (lane & 3) * 2;
#pragma unroll
                for (int h = 0; h < 2; h++) {
                    const int m = mrow + h * 8;
                    const int o = m >> 2, d = m & 3;
                    float v0 = acc[mi][fi][h * 2 + 0];
                    float v1 = acc[mi][fi][h * 2 + 1];
                    float s0 = v0 * v0, s1 = v1 * v1;
                    s0 += __shfl_xor_sync(~0u, s0, 4); s0 += __shfl_xor_sync(~0u, s0, 8);
                    s1 += __shfl_xor_sync(~0u, s1, 4); s1 += __shfl_xor_sync(~0u, s1, 8);
                    v0 *= 1.f / fmaxf(sqrtf(s0), EPS_N);
                    v1 *= 1.f / fmaxf(sqrtf(s1), EPS_N);
                    size_t p0 = (size_t)(bcol * 4 + d) * 1024 + o;
                    size_t p1 = (size_t)((bcol + 1) * 4 + d) * 1024 + o;
                    __half h0 = __float2half(v0), h1 = __float2half(v1);
                    Voh[p0] = h0; Vol[p0] = __float2half(v0 - __half2float(h0));
                    Voh[p1] = h1; Vol[p1] = __float2half(v1 - __half2float(h1));
                }
            }
        }
    } else {
        // rows n=(b,d), cols i. Normalize over n-quads: lanes {l, l^4, l^8}.
#pragma unroll
        for (int mi = 0; mi < 2; mi++) {
            const int nrow = m0 + wm * 32 + mi * 16 + (lane >> 2);
            const int d = nrow & 3;
#pragma unroll
            for (int fi = 0; fi < 8; fi++) {
                const int icol = n0 + wn * 64 + fi * 8 + (lane & 3) * 2;
                const float om0 = omega[icol * 4 + d];
                const float om1 = omega[icol * 4 + 4 + d];
#pragma unroll
                for (int h = 0; h < 2; h++) {
                    const int n = nrow + h * 8;
                    float v0 = acc[mi][fi][h * 2 + 0] + om0;
                    float v1 = acc[mi][fi][h * 2 + 1] + om1;
                    float s0 = v0 * v0, s1 = v1 * v1;
                    s0 += __shfl_xor_sync(~0u, s0, 4); s0 += __shfl_xor_sync(~0u, s0, 8);
                    s1 += __shfl_xor_sync(~0u, s1, 4); s1 += __shfl_xor_sync(~0u, s1, 8);
                    v0 *= 1.f / fmaxf(sqrtf(s0), EPS_N);
                    v1 *= 1.f / fmaxf(sqrtf(s1), EPS_N);
                    if (MODE == 2) {
                        out[(size_t)(n >> 2) * 4096 + icol * 4 + d] = v0;
                        out[(size_t)(n >> 2) * 4096 + (icol + 1) * 4 + d] = v1;
                    } else {
                        __half h0 = __float2half(v0), h1 = __float2half(v1);
                        __half2 hh; hh.x = h0; hh.y = h1;
                        *(__half2*)(Voh + (size_t)n * 1024 + icol) = hh;
                        __half2 ll;
                        ll.x = __float2half(v0 - __half2float(h0));
                        ll.y = __float2half(v1 - __half2float(h1));
                        *(__half2*)(Vol + (size_t)n * 1024 + icol) = ll;
                    }
                }
            }
        }
    }
}

// ---------------------------------------------------------------------------
// Launch
// ---------------------------------------------------------------------------
extern "C" void kernel_launch(void* const* d_in, const int* in_sizes, int n_in,
                              void* d_out, int out_size) {
    const float* x     = (const float*)d_in[0];   // [B, IN]
    const float* W_in  = (const float*)d_in[1];   // [IN, OUT, D]
    const float* omega = (const float*)d_in[2];   // [OUT, D]
    const float* coup  = (const float*)d_in[3];   // [OUT, OUT]
    float* out = (float*)d_out;                   // [B, OUT, D]

    cudaFuncSetAttribute(gemm_f16<0>, cudaFuncAttributeMaxDynamicSharedMemorySize, DSMEM);
    cudaFuncSetAttribute(gemm_f16<1>, cudaFuncAttributeMaxDynamicSharedMemorySize, DSMEM);
    cudaFuncSetAttribute(gemm_f16<2>, cudaFuncAttributeMaxDynamicSharedMemorySize, DSMEM);

    prep_kt<<<(OUT_SZ * OUT_SZ) / 256, 256>>>(coup);
    prep_x<<<(B_SZ * IN_SZ) / 256, 256>>>(x);
    prep_wt<<<dim3(MTOT_I / 32, IN_SZ / 32), 256>>>(W_in);

    // init: M = 4096 (m=(o,d)), N = 8192 (b)
    gemm_f16<0><<<dim3(B_SZ / BTN, MTOT_I / BTM), NTHR, DSMEM>>>(0, omega, out);

    // steps: M = 32768 (n rows), N = 1024 (i); x-dim (i blocks) fastest -> A-tile L2 reuse
    dim3 sgrid(OUT_SZ / BTN, NROW / BTM);
    int s = 0;
    for (int t = 0; t < NSTEPS - 1; t++) {
        gemm_f16<1><<<sgrid, NTHR, DSMEM>>>(s, omega, out);
        s ^= 1;
    }
    gemm_f16<2><<<sgrid, NTHR, DSMEM>>>(s, omega, out);
}

// round 13
// speedup vs baseline: 2.3253x; 1.0629x over previous
#include <cuda_runtime.h>
#include <cuda_fp16.h>
#include <math.h>
#include <stdint.h>

// ---------------- problem constants ----------------
#define B_SZ   8192
#define OUT_SZ 1024
#define IN_SZ  1024
#define D_SZ   4
#define NSTEPS 8
#define NROW   (B_SZ * D_SZ)          /* 32768 state rows n = b*4+d */
#define MTOT_I (OUT_SZ * D_SZ)        /* 4096 init-GEMM M */
#define EPS_N  1e-12f

// ---------------- tiling ----------------
#define BTM  128                      /* CTA tile M */
#define BTN  256                      /* CTA tile N */
#define KCH  64                       /* k per chunk */
#define NCHUNK 16                     /* K = 1024 */
#define NTHR 512                      /* 16 warps: 4 (m) x 4 (n), warp tile 32x64 */
#define STAGES 2
// stage layout: Ah 16KB | Al 16KB | Bh 32KB | Bl 32KB = 96KB
#define A_LO_OFF 16384
#define B_OFF    32768
#define B_SUB    32768
#define STG_BYTES 98304
#define DSMEM (STAGES * STG_BYTES + 1024)

#define SWZ(o) ((o) ^ (((o) >> 3) & 0x70))

// ---------------- device buffers (split fp16) ----------------
__device__ __half g_Kth[OUT_SZ * OUT_SZ];               // tanh(coupling)+I, [i][j]
__device__ __half g_Ktl[OUT_SZ * OUT_SZ];
__device__ __half g_Wth[(size_t)MTOT_I * IN_SZ];        // W transposed [m=(o,d)][k]
__device__ __half g_Wtl[(size_t)MTOT_I * IN_SZ];
__device__ __half g_xh[(size_t)B_SZ * IN_SZ];           // x [b][k]
__device__ __half g_xl[(size_t)B_SZ * IN_SZ];
__device__ __half g_Vh[2][(size_t)NROW * OUT_SZ];       // state [n][j]
__device__ __half g_Vl[2][(size_t)NROW * OUT_SZ];

// ---------------- PTX helpers (baseline, sm_80-era) ----------------
__device__ __forceinline__ uint32_t smem_u32(const void* p) {
    uint32_t a;
    asm("{ .reg .u64 t; cvta.to.shared.u64 t, %1; cvt.u32.u64 %0, t; }" : "=r"(a) : "l"(p));
    return a;
}
__device__ __forceinline__ void cpasync16(uint32_t dst, const void* src) {
    asm volatile("cp.async.cg.shared.global [%0], [%1], 16;" :: "r"(dst), "l"(src));
}
#define CP_COMMIT() asm volatile("cp.async.commit_group;" ::: "memory")
#define CP_WAIT1()  asm volatile("cp.async.wait_group 1;" ::: "memory")

__device__ __forceinline__ void ldsm4(uint32_t* r, uint32_t addr) {
    asm volatile("ldmatrix.sync.aligned.m8n8.x4.shared.b16 {%0,%1,%2,%3}, [%4];"
                 : "=r"(r[0]), "=r"(r[1]), "=r"(r[2]), "=r"(r[3]) : "r"(addr));
}
__device__ __forceinline__ void mma16816(float* d, const uint32_t* a, const uint32_t* b) {
    asm volatile(
        "mma.sync.aligned.m16n8k16.row.col.f32.f16.f16.f32 "
        "{%0,%1,%2,%3}, {%4,%5,%6,%7}, {%8,%9}, {%0,%1,%2,%3};"
        : "+f"(d[0]), "+f"(d[1]), "+f"(d[2]), "+f"(d[3])
        : "r"(a[0]), "r"(a[1]), "r"(a[2]), "r"(a[3]), "r"(b[0]), "r"(b[1]));
}

// ---------------------------------------------------------------------------
// Prep kernels: build split-fp16 operands.
// ---------------------------------------------------------------------------
__global__ void prep_kt(const float* __restrict__ coup) {
    int idx = blockIdx.x * 256 + threadIdx.x;
    int i = idx >> 10, j = idx & 1023;
    float t = tanhf(coup[idx]) + (i == j ? 1.0f : 0.0f);
    __half h = __float2half(t);
    g_Kth[idx] = h;
    g_Ktl[idx] = __float2half(t - __half2float(h));
}

__global__ void prep_x(const float* __restrict__ x) {
    size_t idx = (size_t)blockIdx.x * 256 + threadIdx.x;
    float v = x[idx];
    __half h = __float2half(v);
    g_xh[idx] = h;
    g_xl[idx] = __float2half(v - __half2float(h));
}

// W[k][m] (1024 x 4096 row-major) -> Wt[m][k] split
__global__ void prep_wt(const float* __restrict__ W) {
    __shared__ float t[32][33];
    int tx = threadIdx.x & 31, ty = threadIdx.x >> 5;   // ty 0..7
    int m0 = blockIdx.x * 32, k0 = blockIdx.y * 32;
#pragma unroll
    for (int i = 0; i < 32; i += 8)
        t[ty + i][tx] = W[(size_t)(k0 + ty + i) * MTOT_I + m0 + tx];
    __syncthreads();
#pragma unroll
    for (int i = 0; i < 32; i += 8) {
        float v = t[tx][ty + i];
        __half h = __float2half(v);
        size_t off = (size_t)(m0 + ty + i) * IN_SZ + k0 + tx;
        g_Wth[off] = h;
        g_Wtl[off] = __float2half(v - __half2float(h));
    }
}

// ---------------------------------------------------------------------------
// Fused split-fp16 GEMM + normalize epilogue.
// C[m][n] = sum_k A[m][k]*B[n][k]  (3-pass split accumulate, fp32)
// MODE 0: init   A=Wt[m=(o,d)][k], B=x[b][k];  write V0[(b*4+d)][o] (norm over m-quads)
// MODE 1: step   A=Vt[n][j],       B=K'[i][j]; write Vout[n][i]     (norm over n-quads)
// MODE 2: step final -> write d_out[b][i][d] fp32
// ---------------------------------------------------------------------------
template <int MODE>
__global__ __launch_bounds__(NTHR, 1)
void gemm_f16(int sIn, const float* __restrict__ omega, float* __restrict__ out) {
    extern __shared__ char dsm_raw[];
    char* dsm = (char*)(((uintptr_t)dsm_raw + 1023) & ~(uintptr_t)1023);
    const uint32_t smemBase = smem_u32(dsm);

    const __half* __restrict__ Ah;
    const __half* __restrict__ Al;
    const __half* __restrict__ Bh;
    const __half* __restrict__ Bl;
    __half* __restrict__ Voh;
    __half* __restrict__ Vol;
    if (MODE == 0) {
        Ah = g_Wth; Al = g_Wtl; Bh = g_xh; Bl = g_xl;
        Voh = g_Vh[0]; Vol = g_Vl[0];
    } else {
        Ah = g_Vh[sIn]; Al = g_Vl[sIn]; Bh = g_Kth; Bl = g_Ktl;
        Voh = g_Vh[sIn ^ 1]; Vol = g_Vl[sIn ^ 1];
    }

    const int tid = threadIdx.x;
    const int lane = tid & 31;
    const int w = tid >> 5;
    const int wm = w & 3;        // 4 m-warps of 32 rows
    const int wn = w >> 2;       // 4 n-warps of 64 cols
    const int m0 = blockIdx.y * BTM;
    const int n0 = blockIdx.x * BTN;

    // ldmatrix per-thread UNSWIZZLED base offsets; swizzle applied per access.
    uint32_t aBase[2], bBase[4];
#pragma unroll
    for (int mi = 0; mi < 2; mi++) {
        int r = wm * 32 + mi * 16 + (lane & 7) + ((lane >> 3) & 1) * 8;
        int cc = (lane >> 4);
        aBase[mi] = (uint32_t)(r * 128 + cc * 16);
    }
#pragma unroll
    for (int nj = 0; nj < 4; nj++) {
        int r = wn * 64 + nj * 16 + (lane & 7) + ((lane >> 4) << 3);
        int cc = (lane >> 3) & 1;
        bBase[nj] = (uint32_t)(r * 128 + cc * 16);
    }

    float acc[2][8][4];
#pragma unroll
    for (int a = 0; a < 2; a++)
#pragma unroll
        for (int b = 0; b < 8; b++)
#pragma unroll
            for (int c = 0; c < 4; c++) acc[a][b][c] = 0.f;

    // chunk copy (KCH=64): sub-tiles Ah|Al (16KB each), Bh|Bl (32KB each).
    // Each sub-tile: rows of 128B = 64 halfs of this chunk's k-range.
    auto copy_chunk = [&](int stage, int k0) {
        const uint32_t sb = smemBase + (uint32_t)(stage * STG_BYTES);
        // A: 2048 16B-units (hi then lo), 4 per thread
#pragma unroll
        for (int i = 0; i < 4; i++) {
            int u = tid + i * NTHR;
            int sub = u >> 10;                 // 0 = hi, 1 = lo
            int r = (u & 1023) >> 3, cc = u & 7;
            const __half* src = (sub ? Al : Ah) +
                (size_t)(m0 + r) * 1024 + k0 + cc * 8;
            cpasync16(sb + sub * A_LO_OFF + SWZ((uint32_t)(r * 128 + cc * 16)), src);
        }
        // B: 4096 16B-units (hi then lo), 8 per thread
#pragma unroll
        for (int i = 0; i < 8; i++) {
            int u = tid + i * NTHR;
            int sub = u >> 11;
            int r = (u & 2047) >> 3, cc = u & 7;
            const __half* src = (sub ? Bl : Bh) +
                (size_t)(n0 + r) * 1024 + k0 + cc * 8;
            cpasync16(sb + B_OFF + sub * B_SUB + SWZ((uint32_t)(r * 128 + cc * 16)), src);
        }
    };

    copy_chunk(0, 0);  CP_COMMIT();
    copy_chunk(1, KCH); CP_COMMIT();

    for (int c = 0; c < NCHUNK; c++) {
        CP_WAIT1();
        __syncthreads();
        const uint32_t stg = smemBase + (uint32_t)((c & 1) * STG_BYTES);

#pragma unroll
        for (int s = 0; s < 4; s++) {
            const uint32_t ks = (uint32_t)(s * 32);
            uint32_t ah[2][4], al[2][4];
#pragma unroll
            for (int mi = 0; mi < 2; mi++) {
                ldsm4(ah[mi], stg + SWZ(aBase[mi] + ks));
                ldsm4(al[mi], stg + A_LO_OFF + SWZ(aBase[mi] + ks));
            }
            // per-nj B fragments: only 8 B regs live at a time (reg pressure)
#pragma unroll
            for (int nj = 0; nj < 4; nj++) {
                uint32_t bh[4], bl[4];
                ldsm4(bh, stg + B_OFF + SWZ(bBase[nj] + ks));
                ldsm4(bl, stg + B_OFF + B_SUB + SWZ(bBase[nj] + ks));
#pragma unroll
                for (int mi = 0; mi < 2; mi++) {
                    mma16816(acc[mi][2 * nj + 0], ah[mi], &bh[0]);
                    mma16816(acc[mi][2 * nj + 1], ah[mi], &bh[2]);
                    mma16816(acc[mi][2 * nj + 0], ah[mi], &bl[0]);
                    mma16816(acc[mi][2 * nj + 1], ah[mi], &bl[2]);
                    mma16816(acc[mi][2 * nj + 0], al[mi], &bh[0]);
                    mma16816(acc[mi][2 * nj + 1], al[mi], &bh[2]);
                }
            }
        }

        if (c + 2 < NCHUNK) {
            __syncthreads();               // all reads of this stage done
            copy_chunk(c & 1, (c + 2) * KCH);
        }
        CP_COMMIT();
    }

    // ---------------- epilogue ----------------
    if (MODE == 0) {
        // rows m=(o,d), cols b. Normalize over m-quads: lanes {l, l^4, l^8}.
#pragma unroll
        for (int mi = 0; mi < 2; mi++) {
            const int mrow = m0 + wm * 32 + mi * 16 + (lane >> 2);
#pragma unroll
            for (int fi = 0; fi < 8; fi++) {
                const int bcol = n0 + wn * 64 + fi * 8 + (lane & 3) * 2;
#pragma unroll
                for (int h = 0; h < 2; h++) {
                    const int m = mrow + h * 8;
                    const int o = m >> 2, d = m & 3;
                    float v0 = acc[mi][fi][h * 2 + 0];
                    float v1 = acc[mi][fi][h * 2 + 1];
                    float s0 = v0 * v0, s1 = v1 * v1;
                    s0 += __shfl_xor_sync(~0u, s0, 4); s0 += __shfl_xor_sync(~0u, s0, 8);
                    s1 += __shfl_xor_sync(~0u, s1, 4); s1 += __shfl_xor_sync(~0u, s1, 8);
                    v0 *= 1.f / fmaxf(sqrtf(s0), EPS_N);
                    v1 *= 1.f / fmaxf(sqrtf(s1), EPS_N);
                    size_t p0 = (size_t)(bcol * 4 + d) * 1024 + o;
                    size_t p1 = (size_t)((bcol + 1) * 4 + d) * 1024 + o;
                    __half h0 = __float2half(v0), h1 = __float2half(v1);
                    Voh[p0] = h0; Vol[p0] = __float2half(v0 - __half2float(h0));
                    Voh[p1] = h1; Vol[p1] = __float2half(v1 - __half2float(h1));
                }
            }
        }
    } else {
        // rows n=(b,d), cols i. Normalize over n-quads: lanes {l, l^4, l^8}.
#pragma unroll
        for (int mi = 0; mi < 2; mi++) {
            const int nrow = m0 + wm * 32 + mi * 16 + (lane >> 2);
            const int d = nrow & 3;
#pragma unroll
            for (int fi = 0; fi < 8; fi++) {
                const int icol = n0 + wn * 64 + fi * 8 + (lane & 3) * 2;
                const float om0 = omega[icol * 4 + d];
                const float om1 = omega[icol * 4 + 4 + d];
#pragma unroll
                for (int h = 0; h < 2; h++) {
                    const int n = nrow + h * 8;
                    float v0 = acc[mi][fi][h * 2 + 0] + om0;
                    float v1 = acc[mi][fi][h * 2 + 1] + om1;
                    float s0 = v0 * v0, s1 = v1 * v1;
                    s0 += __shfl_xor_sync(~0u, s0, 4); s0 += __shfl_xor_sync(~0u, s0, 8);
                    s1 += __shfl_xor_sync(~0u, s1, 4); s1 += __shfl_xor_sync(~0u, s1, 8);
                    v0 *= 1.f / fmaxf(sqrtf(s0), EPS_N);
                    v1 *= 1.f / fmaxf(sqrtf(s1), EPS_N);
                    if (MODE == 2) {
                        out[(size_t)(n >> 2) * 4096 + icol * 4 + d] = v0;
                        out[(size_t)(n >> 2) * 4096 + (icol + 1) * 4 + d] = v1;
                    } else {
                        __half h0 = __float2half(v0), h1 = __float2half(v1);
                        __half2 hh; hh.x = h0; hh.y = h1;
                        *(__half2*)(Voh + (size_t)n * 1024 + icol) = hh;
                        __half2 ll;
                        ll.x = __float2half(v0 - __half2float(h0));
                        ll.y = __float2half(v1 - __half2float(h1));
                        *(__half2*)(Vol + (size_t)n * 1024 + icol) = ll;
                    }
                }
            }
        }
    }
}

// ---------------------------------------------------------------------------
// Launch
// ---------------------------------------------------------------------------
extern "C" void kernel_launch(void* const* d_in, const int* in_sizes, int n_in,
                              void* d_out, int out_size) {
    const float* x     = (const float*)d_in[0];   // [B, IN]
    const float* W_in  = (const float*)d_in[1];   // [IN, OUT, D]
    const float* omega = (const float*)d_in[2];   // [OUT, D]
    const float* coup  = (const float*)d_in[3];   // [OUT, OUT]
    float* out = (float*)d_out;                   // [B, OUT, D]

    cudaFuncSetAttribute(gemm_f16<0>, cudaFuncAttributeMaxDynamicSharedMemorySize, DSMEM);
    cudaFuncSetAttribute(gemm_f16<1>, cudaFuncAttributeMaxDynamicSharedMemorySize, DSMEM);
    cudaFuncSetAttribute(gemm_f16<2>, cudaFuncAttributeMaxDynamicSharedMemorySize, DSMEM);

    prep_kt<<<(OUT_SZ * OUT_SZ) / 256, 256>>>(coup);
    prep_x<<<(B_SZ * IN_SZ) / 256, 256>>>(x);
    prep_wt<<<dim3(MTOT_I / 32, IN_SZ / 32), 256>>>(W_in);

    // init: M = 4096 (m=(o,d)), N = 8192 (b)
    gemm_f16<0><<<dim3(B_SZ / BTN, MTOT_I / BTM), NTHR, DSMEM>>>(0, omega, out);

    // steps: M = 32768 (n rows), N = 1024 (i); x-dim (i blocks) fastest -> A-tile L2 reuse
    dim3 sgrid(OUT_SZ / BTN, NROW / BTM);
    int s = 0;
    for (int t = 0; t < NSTEPS - 1; t++) {
        gemm_f16<1><<<sgrid, NTHR, DSMEM>>>(s, omega, out);
        s ^= 1;
    }
    gemm_f16<2><<<sgrid, NTHR, DSMEM>>>(s, omega, out);
}

// round 14
// speedup vs baseline: 2.3287x; 1.0015x over previous
#include <cuda_runtime.h>
#include <cuda_fp16.h>
#include <math.h>
#include <stdint.h>

// ---------------- problem constants ----------------
#define B_SZ   8192
#define OUT_SZ 1024
#define IN_SZ  1024
#define D_SZ   4
#define NSTEPS 8
#define NROW   (B_SZ * D_SZ)          /* 32768 state rows n = b*4+d */
#define MTOT_I (OUT_SZ * D_SZ)        /* 4096 init-GEMM M */
#define EPS_N  1e-12f

// ---------------- tiling ----------------
#define BTM  128                      /* CTA tile M */
#define BTN  256                      /* CTA tile N */
#define KCH  64                       /* k per chunk */
#define NCHUNK 16                     /* K = 1024 */
#define NTHR 512                      /* 16 warps: 4 (m) x 4 (n), warp tile 32x64 */
#define STAGES 2
// stage layout: Ah 16KB | Al 16KB | Bh 32KB | Bl 32KB = 96KB
#define A_LO_OFF 16384
#define B_OFF    32768
#define B_SUB    32768
#define STG_BYTES 98304
#define DSMEM (STAGES * STG_BYTES + 1024)

#define SWZ(o) ((o) ^ (((o) >> 3) & 0x70))

// ---------------- device buffers (split fp16) ----------------
__device__ __half g_Kth[OUT_SZ * OUT_SZ];               // tanh(coupling)+I, [i][j]
__device__ __half g_Ktl[OUT_SZ * OUT_SZ];
__device__ __half g_Wth[(size_t)MTOT_I * IN_SZ];        // W transposed [m=(o,d)][k]
__device__ __half g_Wtl[(size_t)MTOT_I * IN_SZ];
__device__ __half g_xh[(size_t)B_SZ * IN_SZ];           // x [b][k]
__device__ __half g_xl[(size_t)B_SZ * IN_SZ];
__device__ __half g_Vh[2][(size_t)NROW * OUT_SZ];       // state [n][j]
__device__ __half g_Vl[2][(size_t)NROW * OUT_SZ];

// ---------------- PTX helpers (baseline, sm_80-era) ----------------
__device__ __forceinline__ uint32_t smem_u32(const void* p) {
    uint32_t a;
    asm("{ .reg .u64 t; cvta.to.shared.u64 t, %1; cvt.u32.u64 %0, t; }" : "=r"(a) : "l"(p));
    return a;
}
__device__ __forceinline__ void cpasync16(uint32_t dst, const void* src) {
    asm volatile("cp.async.cg.shared.global [%0], [%1], 16;" :: "r"(dst), "l"(src));
}
#define CP_COMMIT() asm volatile("cp.async.commit_group;" ::: "memory")
#define CP_WAIT1()  asm volatile("cp.async.wait_group 1;" ::: "memory")

__device__ __forceinline__ void ldsm4(uint32_t* r, uint32_t addr) {
    asm volatile("ldmatrix.sync.aligned.m8n8.x4.shared.b16 {%0,%1,%2,%3}, [%4];"
                 : "=r"(r[0]), "=r"(r[1]), "=r"(r[2]), "=r"(r[3]) : "r"(addr));
}
__device__ __forceinline__ void mma16816(float* d, const uint32_t* a, const uint32_t* b) {
    asm volatile(
        "mma.sync.aligned.m16n8k16.row.col.f32.f16.f16.f32 "
        "{%0,%1,%2,%3}, {%4,%5,%6,%7}, {%8,%9}, {%0,%1,%2,%3};"
        : "+f"(d[0]), "+f"(d[1]), "+f"(d[2]), "+f"(d[3])
        : "r"(a[0]), "r"(a[1]), "r"(a[2]), "r"(a[3]), "r"(b[0]), "r"(b[1]));
}

// ---------------------------------------------------------------------------
// Prep kernels: build split-fp16 operands.
// ---------------------------------------------------------------------------
__global__ void prep_kt(const float* __restrict__ coup) {
    int idx = blockIdx.x * 256 + threadIdx.x;
    int i = idx >> 10, j = idx & 1023;
    float t = tanhf(coup[idx]) + (i == j ? 1.0f : 0.0f);
    __half h = __float2half(t);
    g_Kth[idx] = h;
    g_Ktl[idx] = __float2half(t - __half2float(h));
}

__global__ void prep_x(const float* __restrict__ x) {
    size_t idx = (size_t)blockIdx.x * 256 + threadIdx.x;
    float v = x[idx];
    __half h = __float2half(v);
    g_xh[idx] = h;
    g_xl[idx] = __float2half(v - __half2float(h));
}

// W[k][m] (1024 x 4096 row-major) -> Wt[m][k] split
__global__ void prep_wt(const float* __restrict__ W) {
    __shared__ float t[32][33];
    int tx = threadIdx.x & 31, ty = threadIdx.x >> 5;   // ty 0..7
    int m0 = blockIdx.x * 32, k0 = blockIdx.y * 32;
#pragma unroll
    for (int i = 0; i < 32; i += 8)
        t[ty + i][tx] = W[(size_t)(k0 + ty + i) * MTOT_I + m0 + tx];
    __syncthreads();
#pragma unroll
    for (int i = 0; i < 32; i += 8) {
        float v = t[tx][ty + i];
        __half h = __float2half(v);
        size_t off = (size_t)(m0 + ty + i) * IN_SZ + k0 + tx;
        g_Wth[off] = h;
        g_Wtl[off] = __float2half(v - __half2float(h));
    }
}

// ---------------------------------------------------------------------------
// Fused split-fp16 GEMM + normalize epilogue.
// C[m][n] = sum_k A[m][k]*B[n][k]  (3-pass split accumulate, fp32)
// MODE 0: init   A=Wt[m=(o,d)][k], B=x[b][k];  write V0[(b*4+d)][o] (norm over m-quads)
// MODE 1: step   A=Vt[n][j],       B=K'[i][j]; write Vout[n][i]     (norm over n-quads)
// MODE 2: step final -> write d_out[b][i][d] fp32
// ---------------------------------------------------------------------------
template <int MODE>
__global__ __launch_bounds__(NTHR, 1)
void gemm_f16(int sIn, const float* __restrict__ omega, float* __restrict__ out) {
    extern __shared__ char dsm_raw[];
    char* dsm = (char*)(((uintptr_t)dsm_raw + 1023) & ~(uintptr_t)1023);
    const uint32_t smemBase = smem_u32(dsm);

    const __half* __restrict__ Ah;
    const __half* __restrict__ Al;
    const __half* __restrict__ Bh;
    const __half* __restrict__ Bl;
    __half* __restrict__ Voh;
    __half* __restrict__ Vol;
    if (MODE == 0) {
        Ah = g_Wth; Al = g_Wtl; Bh = g_xh; Bl = g_xl;
        Voh = g_Vh[0]; Vol = g_Vl[0];
    } else {
        Ah = g_Vh[sIn]; Al = g_Vl[sIn]; Bh = g_Kth; Bl = g_Ktl;
        Voh = g_Vh[sIn ^ 1]; Vol = g_Vl[sIn ^ 1];
    }

    const int tid = threadIdx.x;
    const int lane = tid & 31;
    const int w = tid >> 5;
    const int wm = w & 3;        // 4 m-warps of 32 rows
    const int wn = w >> 2;       // 4 n-warps of 64 cols
    const int m0 = blockIdx.y * BTM;
    const int n0 = blockIdx.x * BTN;

    // ldmatrix per-thread UNSWIZZLED base offsets; swizzle applied per access.
    uint32_t aBase[2], bBase[4];
#pragma unroll
    for (int mi = 0; mi < 2; mi++) {
        int r = wm * 32 + mi * 16 + (lane & 7) + ((lane >> 3) & 1) * 8;
        int cc = (lane >> 4);
        aBase[mi] = (uint32_t)(r * 128 + cc * 16);
    }
#pragma unroll
    for (int nj = 0; nj < 4; nj++) {
        int r = wn * 64 + nj * 16 + (lane & 7) + ((lane >> 4) << 3);
        int cc = (lane >> 3) & 1;
        bBase[nj] = (uint32_t)(r * 128 + cc * 16);
    }

    float acc[2][8][4];
#pragma unroll
    for (int a = 0; a < 2; a++)
#pragma unroll
        for (int b = 0; b < 8; b++)
#pragma unroll
            for (int c = 0; c < 4; c++) acc[a][b][c] = 0.f;

    // chunk copy (KCH=64): sub-tiles Ah|Al (16KB each), Bh|Bl (32KB each).
    auto copy_chunk = [&](int stage, int k0) {
        const uint32_t sb = smemBase + (uint32_t)(stage * STG_BYTES);
#pragma unroll
        for (int i = 0; i < 4; i++) {
            int u = tid + i * NTHR;
            int sub = u >> 10;                 // 0 = hi, 1 = lo
            int r = (u & 1023) >> 3, cc = u & 7;
            const __half* src = (sub ? Al : Ah) +
                (size_t)(m0 + r) * 1024 + k0 + cc * 8;
            cpasync16(sb + sub * A_LO_OFF + SWZ((uint32_t)(r * 128 + cc * 16)), src);
        }
#pragma unroll
        for (int i = 0; i < 8; i++) {
            int u = tid + i * NTHR;
            int sub = u >> 11;
            int r = (u & 2047) >> 3, cc = u & 7;
            const __half* src = (sub ? Bl : Bh) +
                (size_t)(n0 + r) * 1024 + k0 + cc * 8;
            cpasync16(sb + B_OFF + sub * B_SUB + SWZ((uint32_t)(r * 128 + cc * 16)), src);
        }
    };

    copy_chunk(0, 0);  CP_COMMIT();
    copy_chunk(1, KCH); CP_COMMIT();

    for (int c = 0; c < NCHUNK; c++) {
        CP_WAIT1();
        __syncthreads();
        const uint32_t stg = smemBase + (uint32_t)((c & 1) * STG_BYTES);

#pragma unroll
        for (int s = 0; s < 4; s++) {
            const uint32_t ks = (uint32_t)(s * 32);
            // Batch-load ALL fragments for this 32-k slice (12 ldsm, MLP).
            uint32_t ah[2][4], al[2][4], bh[4][4], bl[4][4];
#pragma unroll
            for (int mi = 0; mi < 2; mi++) {
                ldsm4(ah[mi], stg + SWZ(aBase[mi] + ks));
                ldsm4(al[mi], stg + A_LO_OFF + SWZ(aBase[mi] + ks));
            }
#pragma unroll
            for (int nj = 0; nj < 4; nj++) {
                ldsm4(bh[nj], stg + B_OFF + SWZ(bBase[nj] + ks));
                ldsm4(bl[nj], stg + B_OFF + B_SUB + SWZ(bBase[nj] + ks));
            }
            // Pass-major emission: accumulator reuse distance = 16 MMAs,
            // so no HMMA RAW stalls on the accumulator chain.
            // pass 1: ah * bh
#pragma unroll
            for (int nj = 0; nj < 4; nj++)
#pragma unroll
                for (int mi = 0; mi < 2; mi++) {
                    mma16816(acc[mi][2 * nj + 0], ah[mi], &bh[nj][0]);
                    mma16816(acc[mi][2 * nj + 1], ah[mi], &bh[nj][2]);
                }
            // pass 2: ah * bl
#pragma unroll
            for (int nj = 0; nj < 4; nj++)
#pragma unroll
                for (int mi = 0; mi < 2; mi++) {
                    mma16816(acc[mi][2 * nj + 0], ah[mi], &bl[nj][0]);
                    mma16816(acc[mi][2 * nj + 1], ah[mi], &bl[nj][2]);
                }
            // pass 3: al * bh
#pragma unroll
            for (int nj = 0; nj < 4; nj++)
#pragma unroll
                for (int mi = 0; mi < 2; mi++) {
                    mma16816(acc[mi][2 * nj + 0], al[mi], &bh[nj][0]);
                    mma16816(acc[mi][2 * nj + 1], al[mi], &bh[nj][2]);
                }
        }

        if (c + 2 < NCHUNK) {
            __syncthreads();               // all reads of this stage done
            copy_chunk(c & 1, (c + 2) * KCH);
        }
        CP_COMMIT();
    }

    // ---------------- epilogue ----------------
    if (MODE == 0) {
        // rows m=(o,d), cols b. Normalize over m-quads: lanes {l, l^4, l^8}.
#pragma unroll
        for (int mi = 0; mi < 2; mi++) {
            const int mrow = m0 + wm * 32 + mi * 16 + (lane >> 2);
#pragma unroll
            for (int fi = 0; fi < 8; fi++) {
                const int bcol = n0 + wn * 64 + fi * 8 + (lane & 3) * 2;
#pragma unroll
                for (int h = 0; h < 2; h++) {
                    const int m = mrow + h * 8;
                    const int o = m >> 2, d = m & 3;
                    float v0 = acc[mi][fi][h * 2 + 0];
                    float v1 = acc[mi][fi][h * 2 + 1];
                    float s0 = v0 * v0, s1 = v1 * v1;
                    s0 += __shfl_xor_sync(~0u, s0, 4); s0 += __shfl_xor_sync(~0u, s0, 8);
                    s1 += __shfl_xor_sync(~0u, s1, 4); s1 += __shfl_xor_sync(~0u, s1, 8);
                    v0 *= 1.f / fmaxf(sqrtf(s0), EPS_N);
                    v1 *= 1.f / fmaxf(sqrtf(s1), EPS_N);
                    size_t p0 = (size_t)(bcol * 4 + d) * 1024 + o;
                    size_t p1 = (size_t)((bcol + 1) * 4 + d) * 1024 + o;
                    __half h0 = __float2half(v0), h1 = __float2half(v1);
                    Voh[p0] = h0; Vol[p0] = __float2half(v0 - __half2float(h0));
                    Voh[p1] = h1; Vol[p1] = __float2half(v1 - __half2float(h1));
                }
            }
        }
    } else {
        // rows n=(b,d), cols i. Normalize over n-quads: lanes {l, l^4, l^8}.
#pragma unroll
        for (int mi = 0; mi < 2; mi++) {
            const int nrow = m0 + wm * 32 + mi * 16 + (lane >> 2);
            const int d = nrow & 3;
#pragma unroll
            for (int fi = 0; fi < 8; fi++) {
                const int icol = n0 + wn * 64 + fi * 8 + (lane & 3) * 2;
                const float om0 = omega[icol * 4 + d];
                const float om1 = omega[icol * 4 + 4 + d];
#pragma unroll
                for (int h = 0; h < 2; h++) {
                    const int n = nrow + h * 8;
                    float v0 = acc[mi][fi][h * 2 + 0] + om0;
                    float v1 = acc[mi][fi][h * 2 + 1] + om1;
                    float s0 = v0 * v0, s1 = v1 * v1;
                    s0 += __shfl_xor_sync(~0u, s0, 4); s0 += __shfl_xor_sync(~0u, s0, 8);
                    s1 += __shfl_xor_sync(~0u, s1, 4); s1 += __shfl_xor_sync(~0u, s1, 8);
                    v0 *= 1.f / fmaxf(sqrtf(s0), EPS_N);
                    v1 *= 1.f / fmaxf(sqrtf(s1), EPS_N);
                    if (MODE == 2) {
                        out[(size_t)(n >> 2) * 4096 + icol * 4 + d] = v0;
                        out[(size_t)(n >> 2) * 4096 + (icol + 1) * 4 + d] = v1;
                    } else {
                        __half h0 = __float2half(v0), h1 = __float2half(v1);
                        __half2 hh; hh.x = h0; hh.y = h1;
                        *(__half2*)(Voh + (size_t)n * 1024 + icol) = hh;
                        __half2 ll;
                        ll.x = __float2half(v0 - __half2float(h0));
                        ll.y = __float2half(v1 - __half2float(h1));
                        *(__half2*)(Vol + (size_t)n * 1024 + icol) = ll;
                    }
                }
            }
        }
    }
}

// ---------------------------------------------------------------------------
// Launch
// ---------------------------------------------------------------------------
extern "C" void kernel_launch(void* const* d_in, const int* in_sizes, int n_in,
                              void* d_out, int out_size) {
    const float* x     = (const float*)d_in[0];   // [B, IN]
    const float* W_in  = (const float*)d_in[1];   // [IN, OUT, D]
    const float* omega = (const float*)d_in[2];   // [OUT, D]
    const float* coup  = (const float*)d_in[3];   // [OUT, OUT]
    float* out = (float*)d_out;                   // [B, OUT, D]

    cudaFuncSetAttribute(gemm_f16<0>, cudaFuncAttributeMaxDynamicSharedMemorySize, DSMEM);
    cudaFuncSetAttribute(gemm_f16<1>, cudaFuncAttributeMaxDynamicSharedMemorySize, DSMEM);
    cudaFuncSetAttribute(gemm_f16<2>, cudaFuncAttributeMaxDynamicSharedMemorySize, DSMEM);

    prep_kt<<<(OUT_SZ * OUT_SZ) / 256, 256>>>(coup);
    prep_x<<<(B_SZ * IN_SZ) / 256, 256>>>(x);
    prep_wt<<<dim3(MTOT_I / 32, IN_SZ / 32), 256>>>(W_in);

    // init: M = 4096 (m=(o,d)), N = 8192 (b)
    gemm_f16<0><<<dim3(B_SZ / BTN, MTOT_I / BTM), NTHR, DSMEM>>>(0, omega, out);

    // steps: M = 32768 (n rows), N = 1024 (i); x-dim (i blocks) fastest -> A-tile L2 reuse
    dim3 sgrid(OUT_SZ / BTN, NROW / BTM);
    int s = 0;
    for (int t = 0; t < NSTEPS - 1; t++) {
        gemm_f16<1><<<sgrid, NTHR, DSMEM>>>(s, omega, out);
        s ^= 1;
    }
    gemm_f16<2><<<sgrid, NTHR, DSMEM>>>(s, omega, out);
}